// round 10
// baseline (speedup 1.0000x reference)
#include <cuda_runtime.h>
#include <cuda_fp16.h>

#define BB 8192
#define NW 4
#define LL 16
#define EE 128
#define HH 128
#define VV 64
#define BN_TOT (BB*NW)
#define G4H 512

typedef unsigned int u32;

__device__ __align__(16) float g_G[VV * G4H];
__device__ __align__(16) float g_reps[(size_t)BN_TOT * HH];
__device__ int g_perm[BN_TOT];
__device__ int g_cursor[16];

// ---- dynamic smem map for k_lstm (bytes) ----
#define SM_W   0            // W_hh f16 [512][128], row stride 256B, XOR-swizzled
#define SM_G   131072       // G f16 [64][514] (stride 1028B)
#define SM_WID 196864       // u8 [128][16]
#define SM_LEN 198912       // u8 [128]
#define SM_BN  199040       // int [128]
#define SM_BYTES 199552

__device__ __forceinline__ float tanha(float x) {
    float y; asm("tanh.approx.f32 %0, %1;" : "=f"(y) : "f"(x)); return y;
}
__device__ __forceinline__ float sigma_(float x) { return fmaf(0.5f, tanha(0.5f * x), 0.5f); }
__device__ __forceinline__ float sigm_exact(float x) { return __fdividef(1.f, 1.f + __expf(-x)); }

__device__ __forceinline__ u32 s2u(const void* p) {
    u32 a; asm("{.reg .u64 t; cvta.to.shared.u64 t, %1; cvt.u32.u64 %0, t;}" : "=r"(a) : "l"(p));
    return a;
}
__device__ __forceinline__ void ldsm4(u32* r, u32 addr) {
    asm volatile("ldmatrix.sync.aligned.m8n8.x4.shared.b16 {%0,%1,%2,%3}, [%4];"
        : "=r"(r[0]), "=r"(r[1]), "=r"(r[2]), "=r"(r[3]) : "r"(addr));
}
__device__ __forceinline__ void mma16816(float* c, const u32* a, const u32* b) {
    asm volatile("mma.sync.aligned.m16n8k16.row.col.f32.f16.f16.f32 "
        "{%0,%1,%2,%3}, {%4,%5,%6,%7}, {%8,%9}, {%0,%1,%2,%3};"
        : "+f"(c[0]), "+f"(c[1]), "+f"(c[2]), "+f"(c[3])
        : "r"(a[0]), "r"(a[1]), "r"(a[2]), "r"(a[3]), "r"(b[0]), "r"(b[1]));
}
__device__ __forceinline__ u32 packh2(float a, float b) {
    __half2 h = __floats2half2_rn(a, b);
    return *(u32*)&h;
}

// ---- length histogram (desc bins) + scan ----
__global__ void k_prep(const int* __restrict__ lengths) {
    __shared__ int bins[16][33];
    int tid = threadIdx.x, w = tid >> 5;
    for (int i = tid; i < 16 * 33; i += 1024) (&bins[0][0])[i] = 0;
    __syncthreads();
    for (int i = tid; i < BN_TOT; i += 1024)
        atomicAdd(&bins[16 - lengths[i]][w], 1);
    __syncthreads();
    if (tid < 16) {
        int s = 0;
        for (int ww = 0; ww < 32; ++ww) s += bins[tid][ww];
        bins[tid][32] = s;
    }
    __syncthreads();
    if (tid == 0) {
        int cum = 0;
        for (int b = 0; b < 16; ++b) { g_cursor[b] = cum; cum += bins[b][32]; }
    }
}
__global__ void k_scatter(const int* __restrict__ lengths) {
    __shared__ int cnt[16], base[16];
    int tid = threadIdx.x;
    if (tid < 16) cnt[tid] = 0;
    __syncthreads();
    int bn = blockIdx.x * 256 + tid;
    int bin = 16 - lengths[bn];
    int rank = atomicAdd(&cnt[bin], 1);
    __syncthreads();
    if (tid < 16) base[tid] = atomicAdd(&g_cursor[tid], cnt[tid]);
    __syncthreads();
    g_perm[base[bin] + rank] = bn;
}
// ---- G[v][j] = emb[v].W_ih[j] + b_ih[j] + b_hh[j] ----
__global__ void k_gates(const float* __restrict__ emb, const float* __restrict__ Wih,
                        const float* __restrict__ bih, const float* __restrict__ bhh) {
    int v = blockIdx.x, j = threadIdx.x;
    const float* e = emb + v * EE;
    const float* w = Wih + j * EE;
    float s = bih[j] + bhh[j];
#pragma unroll 8
    for (int k = 0; k < EE; ++k) s = fmaf(e[k], w[k], s);
    g_G[v * G4H + j] = s;
}

// ---- HMMA LSTM: warp = 16 rows, h in registers as A-fragments ----
__global__ __launch_bounds__(256, 1)
void k_lstm(const int* __restrict__ wid_g, const int* __restrict__ len_g,
            const float* __restrict__ Whh) {
    extern __shared__ char sm[];
    const u32 sb = s2u(sm);
    const int tid = threadIdx.x, lane = tid & 31, w = tid >> 5;
    const int gid = lane >> 2, t4 = lane & 3;
    const int base = blockIdx.x * 128;

    // W_hh -> f16 swizzled smem
    for (int i = tid; i < 32768; i += 256) {
        int j = i >> 6, kp = i & 63;
        float2 wv = *(const float2*)(Whh + j * 128 + kp * 2);
        u32 o = (u32)(j * 256 + kp * 4);
        *(__half2*)(sm + SM_W + (o ^ ((o >> 4) & 0x70))) = __floats2half2_rn(wv.x, wv.y);
    }
    // G -> f16 smem (padded stride)
    for (int i = tid; i < VV * 256; i += 256) {
        int v = i >> 8, kp = i & 255;
        float2 gv = *(const float2*)(g_G + v * 512 + kp * 2);
        *(__half2*)(sm + SM_G + v * 1028 + kp * 4) = __floats2half2_rn(gv.x, gv.y);
    }
    if (tid < 128) {
        int bn = g_perm[base + tid];
        ((int*)(sm + SM_BN))[tid] = bn;
        ((unsigned char*)(sm + SM_LEN))[tid] = (unsigned char)len_g[bn];
    }
    __syncthreads();
    for (int i = tid; i < 128 * 16; i += 256) {
        int r = i >> 4, t = i & 15;
        ((unsigned char*)(sm + SM_WID))[i] =
            (unsigned char)wid_g[((const int*)(sm + SM_BN))[r] * 16 + t];
    }
    __syncthreads();

    const unsigned char* LEN = (const unsigned char*)(sm + SM_LEN);
    const unsigned char* WID = (const unsigned char*)(sm + SM_WID);
    const int r0 = 16 * w + gid, r1 = r0 + 8;
    const int l0 = LEN[r0], l1 = LEN[r1];
    const int tw = LEN[16 * w];            // sorted desc: first row = warp max

    // per-lane ldmatrix(B) addressing: rows j0+(lane&7)+((lane>>4)<<3), k half by bit3
    const int jl = (lane & 7) + ((lane >> 4) << 3);
    const u32 wka = (u32)(((lane >> 3) & 1) << 4);
    const u32 wmask = (u32)((lane & 7) << 4);
    const u32 wbase = sb + SM_W;

    float c[8][2][2][2];
    u32 h2[16][2], h2n[16][2];
#pragma unroll
    for (int g8 = 0; g8 < 16; ++g8) { h2[g8][0] = 0u; h2[g8][1] = 0u; }
#pragma unroll
    for (int hh = 0; hh < 8; ++hh)
#pragma unroll
        for (int s = 0; s < 2; ++s) {
            c[hh][s][0][0] = 0.f; c[hh][s][0][1] = 0.f;
            c[hh][s][1][0] = 0.f; c[hh][s][1][1] = 0.f;
        }

    for (int t = 0; t < tw; ++t) {
        int v0 = WID[r0 * 16 + t], v1 = WID[r1 * 16 + t];
        const char* gp0 = sm + SM_G + v0 * 1028 + t4 * 4;
        const char* gp1 = sm + SM_G + v1 * 1028 + t4 * 4;
        bool act0 = (t < l0), act1 = (t < l1);
#pragma unroll
        for (int hh = 0; hh < 8; ++hh) {
            float acc[4][2][4];
            // accumulators init = input gates G (f16 smem)
#pragma unroll
            for (int gt = 0; gt < 4; ++gt)
#pragma unroll
                for (int s = 0; s < 2; ++s) {
                    int cb = (gt * 128 + hh * 16 + s * 8) * 2;
                    float2 f0 = __half22float2(*(const __half2*)(gp0 + cb));
                    float2 f1 = __half22float2(*(const __half2*)(gp1 + cb));
                    acc[gt][s][0] = f0.x; acc[gt][s][1] = f0.y;
                    acc[gt][s][2] = f1.x; acc[gt][s][3] = f1.y;
                }
            // gates += h @ W^T  (A-frags straight from h2 registers)
#pragma unroll
            for (int kc = 0; kc < 8; ++kc) {
                u32 a[4] = { h2[2 * kc][0], h2[2 * kc][1], h2[2 * kc + 1][0], h2[2 * kc + 1][1] };
#pragma unroll
                for (int gt = 0; gt < 4; ++gt) {
                    u32 o = (u32)((gt * 128 + hh * 16 + jl) * 256 + kc * 32) + wka;
                    u32 b[4];
                    ldsm4(b, wbase + (o ^ wmask));
                    mma16816(acc[gt][0], a, b);
                    mma16816(acc[gt][1], a, b + 2);
                }
            }
            // epilogue: thread-local LSTM cell update for 16 hidden units
#pragma unroll
            for (int s = 0; s < 2; ++s) {
                float hn[2][2];
#pragma unroll
                for (int rs = 0; rs < 2; ++rs) {
                    bool act = rs ? act1 : act0;
#pragma unroll
                    for (int cs = 0; cs < 2; ++cs) {
                        float iv = acc[0][s][rs * 2 + cs];
                        float fv = acc[1][s][rs * 2 + cs];
                        float gv = acc[2][s][rs * 2 + cs];
                        float ov = acc[3][s][rs * 2 + cs];
                        float cp = c[hh][s][rs][cs];
                        float cn = fmaf(sigma_(fv), cp, sigma_(iv) * tanha(gv));
                        if (act) c[hh][s][rs][cs] = cn;
                        hn[rs][cs] = sigma_(ov) * tanha(cn);
                    }
                }
                int g8 = 2 * hh + s;
                u32 p0 = packh2(hn[0][0], hn[0][1]);
                u32 p1 = packh2(hn[1][0], hn[1][1]);
                h2n[g8][0] = act0 ? p0 : h2[g8][0];
                h2n[g8][1] = act1 ? p1 : h2[g8][1];
            }
        }
#pragma unroll
        for (int g8 = 0; g8 < 16; ++g8) { h2[g8][0] = h2n[g8][0]; h2[g8][1] = h2n[g8][1]; }
    }

    // reps = final cell state
    const int* BN = (const int*)(sm + SM_BN);
    float* d0 = g_reps + (size_t)BN[r0] * HH;
    float* d1 = g_reps + (size_t)BN[r1] * HH;
#pragma unroll
    for (int hh = 0; hh < 8; ++hh)
#pragma unroll
        for (int s = 0; s < 2; ++s) {
            int col = hh * 16 + s * 8 + t4 * 2;
            *(float2*)(d0 + col) = make_float2(c[hh][s][0][0], c[hh][s][0][1]);
            *(float2*)(d1 + col) = make_float2(c[hh][s][1][0], c[hh][s][1][1]);
        }
}

// ---- head: cos 4x4 -> conv1 relu -> conv2 relu -> scorer -> sigmoid ----
__global__ void k_head(const float* __restrict__ c1w, const float* __restrict__ c1b,
                       const float* __restrict__ c2w, const float* __restrict__ c2b,
                       const float* __restrict__ scw, const float* __restrict__ scb,
                       float* __restrict__ out) {
    int gw = blockIdx.x * 8 + (threadIdx.x >> 5);
    int lane = threadIdx.x & 31;
    if (gw >= BB) return;
    const float* rp = g_reps + (size_t)gw * (NW * HH);
    float4 rv[4];
#pragma unroll
    for (int i = 0; i < 4; ++i) rv[i] = *(const float4*)(rp + i * HH + lane * 4);
    const int pi[10] = {0,0,0,0,1,1,1,2,2,3};
    const int pj[10] = {0,1,2,3,1,2,3,2,3,3};
    float dots[10];
#pragma unroll
    for (int d = 0; d < 10; ++d) {
        float4 a = rv[pi[d]], b = rv[pj[d]];
        float s = a.x*b.x + a.y*b.y + a.z*b.z + a.w*b.w;
#pragma unroll
        for (int o = 16; o; o >>= 1) s += __shfl_xor_sync(0xffffffffu, s, o);
        dots[d] = s;
    }
    if (lane) return;
    float nn[4] = { rsqrtf(dots[0]), rsqrtf(dots[4]), rsqrtf(dots[7]), rsqrtf(dots[9]) };
    const int dmap[4][4] = {{0,1,2,3},{1,4,5,6},{2,5,7,8},{3,6,8,9}};
    float cm[4][4];
#pragma unroll
    for (int i = 0; i < 4; ++i)
#pragma unroll
        for (int j = 0; j < 4; ++j)
            cm[i][j] = dots[dmap[i][j]] * nn[i] * nn[j];
    float o1[4][3][3];
#pragma unroll
    for (int cc = 0; cc < 4; ++cc) {
        float w00 = c1w[cc*4+0], w01 = c1w[cc*4+1], w10 = c1w[cc*4+2], w11 = c1w[cc*4+3];
        float bb = c1b[cc];
#pragma unroll
        for (int y = 0; y < 3; ++y)
#pragma unroll
            for (int x = 0; x < 3; ++x)
                o1[cc][y][x] = fmaxf(bb + w00*cm[y][x] + w01*cm[y][x+1]
                                        + w10*cm[y+1][x] + w11*cm[y+1][x+1], 0.f);
    }
    float score = scb[0];
#pragma unroll
    for (int oc = 0; oc < 8; ++oc) {
        float bb = c2b[oc];
#pragma unroll
        for (int y = 0; y < 2; ++y)
#pragma unroll
            for (int x = 0; x < 2; ++x) {
                float s = bb;
#pragma unroll
                for (int ic = 0; ic < 4; ++ic) {
                    const float* ww = c2w + ((oc*4 + ic) * 4);
                    s += ww[0]*o1[ic][y][x]   + ww[1]*o1[ic][y][x+1]
                       + ww[2]*o1[ic][y+1][x] + ww[3]*o1[ic][y+1][x+1];
                }
                score += fmaxf(s, 0.f) * scw[oc*4 + y*2 + x];
            }
    }
    out[gw] = sigm_exact(score);
}

extern "C" void kernel_launch(void* const* d_in, const int* in_sizes, int n_in,
                              void* d_out, int out_size) {
    const int*   word_ids = (const int*)  d_in[0];
    const int*   lengths  = (const int*)  d_in[1];
    const float* emb      = (const float*)d_in[2];
    const float* Wih      = (const float*)d_in[3];
    const float* Whh      = (const float*)d_in[4];
    const float* bih      = (const float*)d_in[5];
    const float* bhh      = (const float*)d_in[6];
    const float* c1w      = (const float*)d_in[7];
    const float* c1b      = (const float*)d_in[8];
    const float* c2w      = (const float*)d_in[9];
    const float* c2b      = (const float*)d_in[10];
    const float* scw      = (const float*)d_in[11];
    const float* scb      = (const float*)d_in[12];
    float* out = (float*)d_out;

    static int attr_done = 0;
    if (!attr_done) {
        cudaFuncSetAttribute(k_lstm, cudaFuncAttributeMaxDynamicSharedMemorySize, SM_BYTES);
        attr_done = 1;
    }
    k_prep<<<1, 1024>>>(lengths);
    k_scatter<<<BN_TOT/256, 256>>>(lengths);
    k_gates<<<VV, G4H>>>(emb, Wih, bih, bhh);
    k_lstm<<<BN_TOT/128, 256, SM_BYTES>>>(word_ids, lengths, Whh);
    k_head<<<BB/8, 256>>>(c1w, c1b, c2w, c2b, scw, scb, out);
}

// round 11
// speedup vs baseline: 1.1412x; 1.1412x over previous
#include <cuda_runtime.h>
#include <cuda_fp16.h>

#define BB 8192
#define NW 4
#define LL 16
#define EE 128
#define HH 128
#define VV 64
#define BN_TOT (BB*NW)
#define G4H 512

typedef unsigned int u32;

__device__ __align__(16) float g_G[VV * G4H];
__device__ __align__(16) float g_reps[(size_t)BN_TOT * HH];
__device__ int g_perm[BN_TOT];
__device__ int g_cursor[16];

// ---- dynamic smem map (bytes) ----
#define SM_W    0          // W_hh f16 [512][128], 256B rows, XOR swizzle
#define SM_G    131072     // G f16 [64] rows, stride 1028B
#define SM_H    196864     // h f16 [128][128], 256B rows, XOR swizzle
#define SM_WID  229632     // u8 [128][16]
#define SM_LEN  231680     // u8 [128]
#define SM_BYTES 231808

__device__ __forceinline__ float tanha(float x) {
    float y; asm("tanh.approx.f32 %0, %1;" : "=f"(y) : "f"(x)); return y;
}
__device__ __forceinline__ float sigma_(float x) { return fmaf(0.5f, tanha(0.5f * x), 0.5f); }
__device__ __forceinline__ float sigm_exact(float x) { return __fdividef(1.f, 1.f + __expf(-x)); }

__device__ __forceinline__ u32 s2u(const void* p) {
    u32 a; asm("{.reg .u64 t; cvta.to.shared.u64 t, %1; cvt.u32.u64 %0, t;}" : "=r"(a) : "l"(p));
    return a;
}
__device__ __forceinline__ void ldsm4(u32* r, u32 addr) {
    asm volatile("ldmatrix.sync.aligned.m8n8.x4.shared.b16 {%0,%1,%2,%3}, [%4];"
        : "=r"(r[0]), "=r"(r[1]), "=r"(r[2]), "=r"(r[3]) : "r"(addr));
}
__device__ __forceinline__ void mma16816(float* c, const u32* a, const u32* b) {
    asm volatile("mma.sync.aligned.m16n8k16.row.col.f32.f16.f16.f32 "
        "{%0,%1,%2,%3}, {%4,%5,%6,%7}, {%8,%9}, {%0,%1,%2,%3};"
        : "+f"(c[0]), "+f"(c[1]), "+f"(c[2]), "+f"(c[3])
        : "r"(a[0]), "r"(a[1]), "r"(a[2]), "r"(a[3]), "r"(b[0]), "r"(b[1]));
}
__device__ __forceinline__ u32 packh2(float a, float b) {
    __half2 h = __floats2half2_rn(a, b);
    return *(u32*)&h;
}

// ---- length histogram (desc bins) + scan ----
__global__ void k_prep(const int* __restrict__ lengths) {
    __shared__ int bins[16][33];
    int tid = threadIdx.x, w = tid >> 5;
    for (int i = tid; i < 16 * 33; i += 1024) (&bins[0][0])[i] = 0;
    __syncthreads();
    for (int i = tid; i < BN_TOT; i += 1024)
        atomicAdd(&bins[16 - lengths[i]][w], 1);
    __syncthreads();
    if (tid < 16) {
        int s = 0;
        for (int ww = 0; ww < 32; ++ww) s += bins[tid][ww];
        bins[tid][32] = s;
    }
    __syncthreads();
    if (tid == 0) {
        int cum = 0;
        for (int b = 0; b < 16; ++b) { g_cursor[b] = cum; cum += bins[b][32]; }
    }
}
__global__ void k_scatter(const int* __restrict__ lengths) {
    __shared__ int cnt[16], base[16];
    int tid = threadIdx.x;
    if (tid < 16) cnt[tid] = 0;
    __syncthreads();
    int bn = blockIdx.x * 256 + tid;
    int bin = 16 - lengths[bn];
    int rank = atomicAdd(&cnt[bin], 1);
    __syncthreads();
    if (tid < 16) base[tid] = atomicAdd(&g_cursor[tid], cnt[tid]);
    __syncthreads();
    g_perm[base[bin] + rank] = bn;
}
// ---- G[v][j] = emb[v].W_ih[j] + b_ih[j] + b_hh[j] ----
__global__ void k_gates(const float* __restrict__ emb, const float* __restrict__ Wih,
                        const float* __restrict__ bih, const float* __restrict__ bhh) {
    int v = blockIdx.x, j = threadIdx.x;
    const float* e = emb + v * EE;
    const float* w = Wih + j * EE;
    float s = bih[j] + bhh[j];
#pragma unroll 8
    for (int k = 0; k < EE; ++k) s = fmaf(e[k], w[k], s);
    g_G[v * G4H + j] = s;
}

// ---- HMMA LSTM, gate-split warp pairs ----
// CTA = 128 rows, 8 warps = 4 pairs. Pair owns 32 rows; within the pair, warp
// q computes ALL 4 gates for hidden units [64q, 64q+64) (j = 128g + 64q + ...),
// so i/f/g/o stay thread-aligned and c is register-resident. h is exchanged
// through a swizzled SMEM buffer (ldmatrix A-frags), 2 named barriers/step.
__global__ __launch_bounds__(256, 1)
void k_lstm(const int* __restrict__ wid_g, const int* __restrict__ len_g,
            const float* __restrict__ Whh) {
    extern __shared__ char sm[];
    const u32 sb = s2u(sm);
    const int tid = threadIdx.x, lane = tid & 31, w = tid >> 5;
    const int gid = lane >> 2, t4 = lane & 3;
    const int pair = w >> 1, q = w & 1;
    const int base = blockIdx.x * 128;
    const int prow = pair * 32;

    // W_hh -> f16 swizzled smem
    for (int i = tid; i < 32768; i += 256) {
        int j = i >> 6, kp = i & 63;
        float2 wv = *(const float2*)(Whh + j * 128 + kp * 2);
        u32 o = (u32)(j * 256 + kp * 4);
        *(__half2*)(sm + SM_W + (o ^ ((o >> 4) & 0x70))) = __floats2half2_rn(wv.x, wv.y);
    }
    // G -> f16 smem (stride 1028B)
    for (int i = tid; i < VV * 256; i += 256) {
        int v = i >> 8, kp = i & 255;
        float2 gv = *(const float2*)(g_G + v * 512 + kp * 2);
        *(__half2*)(sm + SM_G + v * 1028 + kp * 4) = __floats2half2_rn(gv.x, gv.y);
    }
    // H zero
    for (int i = tid; i < 2048; i += 256)
        ((uint4*)(sm + SM_H))[i] = make_uint4(0, 0, 0, 0);
    if (tid < 128)
        ((unsigned char*)(sm + SM_LEN))[tid] = (unsigned char)len_g[g_perm[base + tid]];
    for (int i = tid; i < 2048; i += 256) {
        int r = i >> 4, t = i & 15;
        ((unsigned char*)(sm + SM_WID))[i] = (unsigned char)wid_g[g_perm[base + r] * 16 + t];
    }
    __syncthreads();

    const unsigned char* LEN = (const unsigned char*)(sm + SM_LEN);
    const unsigned char* WID = (const unsigned char*)(sm + SM_WID);
    int lenr[2][2];
#pragma unroll
    for (int ms = 0; ms < 2; ++ms)
#pragma unroll
        for (int rs = 0; rs < 2; ++rs)
            lenr[ms][rs] = LEN[prow + 16 * ms + gid + 8 * rs];
    const int tw = LEN[prow];   // sorted desc: pair max

    // B (W) addressing — proven in prior round
    const int jl = (lane & 7) + ((lane >> 4) << 3);
    const u32 wka = (u32)(((lane >> 3) & 1) << 4);
    const u32 wmask = (u32)((lane & 7) << 4);
    const u32 Bbase = sb + SM_W + (u32)(64 * q + jl) * 256;
    u32 Blow[8];
#pragma unroll
    for (int kc = 0; kc < 8; ++kc) Blow[kc] = ((u32)(kc * 32) + wka) ^ wmask;

    // A (H) ldmatrix addressing: canonical m16k16 row-major
    const int arow = (lane & 7) + (((lane >> 3) & 1) << 3);
    const u32 xorr = (u32)((lane & 7) << 4);
    const u32 Abase = sb + SM_H + (u32)(prow + arow) * 256;
    u32 Alow[8];
#pragma unroll
    for (int kc = 0; kc < 8; ++kc)
        Alow[kc] = ((u32)(kc * 32 + (((lane >> 4) & 1) << 4))) ^ xorr;

    // H write base: cb = 128q + 32st + 16b + 4t4, XOR gid<<4 hits only bits4-6
    const u32 g4 = (u32)(gid << 4);
    u32 Hw[2][2];
#pragma unroll
    for (int ms = 0; ms < 2; ++ms)
#pragma unroll
        for (int rs = 0; rs < 2; ++rs)
            Hw[ms][rs] = sb + SM_H + (u32)(prow + 16 * ms + gid + 8 * rs) * 256
                       + (u32)(128 * q + 4 * t4);
    const u32 gq = (u32)(128 * q + 4 * t4);

    float c_[4][2][2][2][2];   // [st][ms][b][rs][e]
#pragma unroll
    for (int st = 0; st < 4; ++st)
#pragma unroll
        for (int ms = 0; ms < 2; ++ms)
#pragma unroll
            for (int b = 0; b < 2; ++b) {
                c_[st][ms][b][0][0] = 0.f; c_[st][ms][b][0][1] = 0.f;
                c_[st][ms][b][1][0] = 0.f; c_[st][ms][b][1][1] = 0.f;
            }

    for (int t = 0; t < tw; ++t) {
        int v[2][2];
#pragma unroll
        for (int ms = 0; ms < 2; ++ms)
#pragma unroll
            for (int rs = 0; rs < 2; ++rs)
                v[ms][rs] = WID[(prow + 16 * ms + gid + 8 * rs) * 16 + t];

        // A fragments for the pair's 32 rows (reads H)
        u32 A[2][8][4];
#pragma unroll
        for (int ms = 0; ms < 2; ++ms)
#pragma unroll
            for (int kc = 0; kc < 8; ++kc)
                ldsm4(A[ms][kc], Abase + (u32)(ms * 4096) + Alow[kc]);
        asm volatile("bar.sync %0, 64;" :: "r"(pair + 1) : "memory");  // reads done

#pragma unroll
        for (int st = 0; st < 4; ++st) {
            float acc[4][2][2][4];   // [gate][ms][b][rs*2+e]
#pragma unroll
            for (int g = 0; g < 4; ++g)
#pragma unroll
                for (int ms = 0; ms < 2; ++ms)
#pragma unroll
                    for (int b = 0; b < 2; ++b)
#pragma unroll
                        for (int rs = 0; rs < 2; ++rs) {
                            __half2 hv = *(const __half2*)(sm + SM_G
                                + v[ms][rs] * 1028 + (u32)(256 * g + 32 * st + 16 * b) + gq);
                            float2 f = __half22float2(hv);
                            acc[g][ms][b][rs * 2 + 0] = f.x;
                            acc[g][ms][b][rs * 2 + 1] = f.y;
                        }
#pragma unroll
            for (int kc = 0; kc < 8; ++kc)
#pragma unroll
                for (int g = 0; g < 4; ++g) {
                    u32 B[4];
                    ldsm4(B, Bbase + (u32)(32768 * g + 4096 * st) + Blow[kc]);
#pragma unroll
                    for (int ms = 0; ms < 2; ++ms) {
                        mma16816(acc[g][ms][0], A[ms][kc], B);
                        mma16816(acc[g][ms][1], A[ms][kc], B + 2);
                    }
                }
            // epilogue: cell update + h write (this warp's 64 hidden units)
#pragma unroll
            for (int ms = 0; ms < 2; ++ms)
#pragma unroll
                for (int b = 0; b < 2; ++b)
#pragma unroll
                    for (int rs = 0; rs < 2; ++rs) {
                        bool act = (t < lenr[ms][rs]);
                        float hn[2];
#pragma unroll
                        for (int e = 0; e < 2; ++e) {
                            float iv = acc[0][ms][b][rs * 2 + e];
                            float fv = acc[1][ms][b][rs * 2 + e];
                            float gv = acc[2][ms][b][rs * 2 + e];
                            float ov = acc[3][ms][b][rs * 2 + e];
                            float cp = c_[st][ms][b][rs][e];
                            float cn = fmaf(sigma_(fv), cp, sigma_(iv) * tanha(gv));
                            if (act) c_[st][ms][b][rs][e] = cn;
                            hn[e] = sigma_(ov) * tanha(cn);
                        }
                        if (act)
                            *(u32*)(sm + (Hw[ms][rs] - sb)
                                + ((u32)(32 * st + 16 * b) ^ g4)) = packh2(hn[0], hn[1]);
                    }
        }
        asm volatile("bar.sync %0, 64;" :: "r"(pair + 1) : "memory");  // writes done
    }

    // reps = final cell state
#pragma unroll
    for (int ms = 0; ms < 2; ++ms)
#pragma unroll
        for (int rs = 0; rs < 2; ++rs) {
            int bn = g_perm[base + prow + 16 * ms + gid + 8 * rs];
            float* dst = g_reps + (size_t)bn * HH + 64 * q + 2 * t4;
#pragma unroll
            for (int st = 0; st < 4; ++st)
#pragma unroll
                for (int b = 0; b < 2; ++b)
                    *(float2*)(dst + 16 * st + 8 * b) =
                        make_float2(c_[st][ms][b][rs][0], c_[st][ms][b][rs][1]);
        }
}

// ---- head: cos 4x4 -> conv1 relu -> conv2 relu -> scorer -> sigmoid ----
__global__ void k_head(const float* __restrict__ c1w, const float* __restrict__ c1b,
                       const float* __restrict__ c2w, const float* __restrict__ c2b,
                       const float* __restrict__ scw, const float* __restrict__ scb,
                       float* __restrict__ out) {
    int gw = blockIdx.x * 8 + (threadIdx.x >> 5);
    int lane = threadIdx.x & 31;
    if (gw >= BB) return;
    const float* rp = g_reps + (size_t)gw * (NW * HH);
    float4 rv[4];
#pragma unroll
    for (int i = 0; i < 4; ++i) rv[i] = *(const float4*)(rp + i * HH + lane * 4);
    const int pi[10] = {0,0,0,0,1,1,1,2,2,3};
    const int pj[10] = {0,1,2,3,1,2,3,2,3,3};
    float dots[10];
#pragma unroll
    for (int d = 0; d < 10; ++d) {
        float4 a = rv[pi[d]], b = rv[pj[d]];
        float s = a.x*b.x + a.y*b.y + a.z*b.z + a.w*b.w;
#pragma unroll
        for (int o = 16; o; o >>= 1) s += __shfl_xor_sync(0xffffffffu, s, o);
        dots[d] = s;
    }
    if (lane) return;
    float nn[4] = { rsqrtf(dots[0]), rsqrtf(dots[4]), rsqrtf(dots[7]), rsqrtf(dots[9]) };
    const int dmap[4][4] = {{0,1,2,3},{1,4,5,6},{2,5,7,8},{3,6,8,9}};
    float cm[4][4];
#pragma unroll
    for (int i = 0; i < 4; ++i)
#pragma unroll
        for (int j = 0; j < 4; ++j)
            cm[i][j] = dots[dmap[i][j]] * nn[i] * nn[j];
    float o1[4][3][3];
#pragma unroll
    for (int cc = 0; cc < 4; ++cc) {
        float w00 = c1w[cc*4+0], w01 = c1w[cc*4+1], w10 = c1w[cc*4+2], w11 = c1w[cc*4+3];
        float bb = c1b[cc];
#pragma unroll
        for (int y = 0; y < 3; ++y)
#pragma unroll
            for (int x = 0; x < 3; ++x)
                o1[cc][y][x] = fmaxf(bb + w00*cm[y][x] + w01*cm[y][x+1]
                                        + w10*cm[y+1][x] + w11*cm[y+1][x+1], 0.f);
    }
    float score = scb[0];
#pragma unroll
    for (int oc = 0; oc < 8; ++oc) {
        float bb = c2b[oc];
#pragma unroll
        for (int y = 0; y < 2; ++y)
#pragma unroll
            for (int x = 0; x < 2; ++x) {
                float s = bb;
#pragma unroll
                for (int ic = 0; ic < 4; ++ic) {
                    const float* ww = c2w + ((oc*4 + ic) * 4);
                    s += ww[0]*o1[ic][y][x]   + ww[1]*o1[ic][y][x+1]
                       + ww[2]*o1[ic][y+1][x] + ww[3]*o1[ic][y+1][x+1];
                }
                score += fmaxf(s, 0.f) * scw[oc*4 + y*2 + x];
            }
    }
    out[gw] = sigm_exact(score);
}

extern "C" void kernel_launch(void* const* d_in, const int* in_sizes, int n_in,
                              void* d_out, int out_size) {
    const int*   word_ids = (const int*)  d_in[0];
    const int*   lengths  = (const int*)  d_in[1];
    const float* emb      = (const float*)d_in[2];
    const float* Wih      = (const float*)d_in[3];
    const float* Whh      = (const float*)d_in[4];
    const float* bih      = (const float*)d_in[5];
    const float* bhh      = (const float*)d_in[6];
    const float* c1w      = (const float*)d_in[7];
    const float* c1b      = (const float*)d_in[8];
    const float* c2w      = (const float*)d_in[9];
    const float* c2b      = (const float*)d_in[10];
    const float* scw      = (const float*)d_in[11];
    const float* scb      = (const float*)d_in[12];
    float* out = (float*)d_out;

    static int attr_done = 0;
    if (!attr_done) {
        cudaFuncSetAttribute(k_lstm, cudaFuncAttributeMaxDynamicSharedMemorySize, SM_BYTES);
        attr_done = 1;
    }
    k_prep<<<1, 1024>>>(lengths);
    k_scatter<<<BN_TOT/256, 256>>>(lengths);
    k_gates<<<VV, G4H>>>(emb, Wih, bih, bhh);
    k_lstm<<<BN_TOT/128, 256, SM_BYTES>>>(word_ids, lengths, Whh);
    k_head<<<BB/8, 256>>>(c1w, c1b, c2w, c2b, scw, scb, out);
}

// round 12
// speedup vs baseline: 1.2546x; 1.0994x over previous
#include <cuda_runtime.h>
#include <cuda_fp16.h>

#define BB 8192
#define NW 4
#define LL 16
#define EE 128
#define HH 128
#define VV 64
#define BN_TOT (BB*NW)
#define G4H 512

typedef unsigned int u32;

__device__ __align__(16) float g_G[VV * G4H];
__device__ __align__(16) float g_reps[(size_t)BN_TOT * HH];
__device__ int g_perm[BN_TOT];
__device__ int g_cursor[16];

// ---- dynamic smem map (bytes) ----
#define SM_W    0          // W_hh f16 [512][128], 256B rows, XOR swizzle
#define SM_G    131072     // G f16 [64] rows, stride 1028B
#define SM_H    196864     // h f16 [128][128], 256B rows, XOR swizzle
#define SM_WID  229632     // u8 [128][16]
#define SM_LEN  231680     // u8 [128]
#define SM_BYTES 231808

__device__ __forceinline__ float tanha(float x) {
    float y; asm("tanh.approx.f32 %0, %1;" : "=f"(y) : "f"(x)); return y;
}
__device__ __forceinline__ float sigma_(float x) { return fmaf(0.5f, tanha(0.5f * x), 0.5f); }
__device__ __forceinline__ float sigm_exact(float x) { return __fdividef(1.f, 1.f + __expf(-x)); }

__device__ __forceinline__ u32 s2u(const void* p) {
    u32 a; asm("{.reg .u64 t; cvta.to.shared.u64 t, %1; cvt.u32.u64 %0, t;}" : "=r"(a) : "l"(p));
    return a;
}
__device__ __forceinline__ void ldsm4(u32* r, u32 addr) {
    asm volatile("ldmatrix.sync.aligned.m8n8.x4.shared.b16 {%0,%1,%2,%3}, [%4];"
        : "=r"(r[0]), "=r"(r[1]), "=r"(r[2]), "=r"(r[3]) : "r"(addr));
}
__device__ __forceinline__ void mma16816(float* c, const u32* a, const u32* b) {
    asm volatile("mma.sync.aligned.m16n8k16.row.col.f32.f16.f16.f32 "
        "{%0,%1,%2,%3}, {%4,%5,%6,%7}, {%8,%9}, {%0,%1,%2,%3};"
        : "+f"(c[0]), "+f"(c[1]), "+f"(c[2]), "+f"(c[3])
        : "r"(a[0]), "r"(a[1]), "r"(a[2]), "r"(a[3]), "r"(b[0]), "r"(b[1]));
}
__device__ __forceinline__ u32 packh2(float a, float b) {
    __half2 h = __floats2half2_rn(a, b);
    return *(u32*)&h;
}

// ---- length histogram (desc bins) + scan ----
__global__ void k_prep(const int* __restrict__ lengths) {
    __shared__ int bins[16][33];
    int tid = threadIdx.x, w = tid >> 5;
    for (int i = tid; i < 16 * 33; i += 1024) (&bins[0][0])[i] = 0;
    __syncthreads();
    for (int i = tid; i < BN_TOT; i += 1024)
        atomicAdd(&bins[16 - lengths[i]][w], 1);
    __syncthreads();
    if (tid < 16) {
        int s = 0;
        for (int ww = 0; ww < 32; ++ww) s += bins[tid][ww];
        bins[tid][32] = s;
    }
    __syncthreads();
    if (tid == 0) {
        int cum = 0;
        for (int b = 0; b < 16; ++b) { g_cursor[b] = cum; cum += bins[b][32]; }
    }
}
__global__ void k_scatter(const int* __restrict__ lengths) {
    __shared__ int cnt[16], base[16];
    int tid = threadIdx.x;
    if (tid < 16) cnt[tid] = 0;
    __syncthreads();
    int bn = blockIdx.x * 256 + tid;
    int bin = 16 - lengths[bn];
    int rank = atomicAdd(&cnt[bin], 1);
    __syncthreads();
    if (tid < 16) base[tid] = atomicAdd(&g_cursor[tid], cnt[tid]);
    __syncthreads();
    g_perm[base[bin] + rank] = bn;
}
// ---- G[v][j] = emb[v].W_ih[j] + b_ih[j] + b_hh[j] ----
__global__ void k_gates(const float* __restrict__ emb, const float* __restrict__ Wih,
                        const float* __restrict__ bih, const float* __restrict__ bhh) {
    int v = blockIdx.x, j = threadIdx.x;
    const float* e = emb + v * EE;
    const float* w = Wih + j * EE;
    float s = bih[j] + bhh[j];
#pragma unroll 8
    for (int k = 0; k < EE; ++k) s = fmaf(e[k], w[k], s);
    g_G[v * G4H + j] = s;
}

// ---- HMMA LSTM, gate-split warp pairs, 16 rows/warp ----
// CTA = 128 rows, 16 warps = 8 pairs. Pair owns 16 rows; warp q of the pair
// computes ALL 4 gates for hidden units [64q, 64q+64), so i/f/g/o stay
// thread-aligned and c is register-resident. h exchanged via swizzled SMEM
// (ldmatrix A-frags); 2 named 64-thread barriers per step.
__global__ __launch_bounds__(512, 1)
void k_lstm(const int* __restrict__ wid_g, const int* __restrict__ len_g,
            const float* __restrict__ Whh) {
    extern __shared__ char sm[];
    const u32 sb = s2u(sm);
    const int tid = threadIdx.x, lane = tid & 31, w = tid >> 5;
    const int gid = lane >> 2, t4 = lane & 3;
    const int pair = w >> 1, q = w & 1;
    const int base = blockIdx.x * 128;
    const int prow = pair * 16;

    // W_hh -> f16 swizzled smem
    for (int i = tid; i < 32768; i += 512) {
        int j = i >> 6, kp = i & 63;
        float2 wv = *(const float2*)(Whh + j * 128 + kp * 2);
        u32 o = (u32)(j * 256 + kp * 4);
        *(__half2*)(sm + SM_W + (o ^ ((o >> 4) & 0x70))) = __floats2half2_rn(wv.x, wv.y);
    }
    // G -> f16 smem (stride 1028B)
    for (int i = tid; i < VV * 256; i += 512) {
        int v = i >> 8, kp = i & 255;
        float2 gv = *(const float2*)(g_G + v * 512 + kp * 2);
        *(__half2*)(sm + SM_G + v * 1028 + kp * 4) = __floats2half2_rn(gv.x, gv.y);
    }
    // H zero
    for (int i = tid; i < 2048; i += 512)
        ((uint4*)(sm + SM_H))[i] = make_uint4(0, 0, 0, 0);
    if (tid < 128)
        ((unsigned char*)(sm + SM_LEN))[tid] = (unsigned char)len_g[g_perm[base + tid]];
    for (int i = tid; i < 2048; i += 512) {
        int r = i >> 4, t = i & 15;
        ((unsigned char*)(sm + SM_WID))[i] = (unsigned char)wid_g[g_perm[base + r] * 16 + t];
    }
    __syncthreads();

    const unsigned char* LEN = (const unsigned char*)(sm + SM_LEN);
    const unsigned char* WID = (const unsigned char*)(sm + SM_WID);
    int lenr[2];
#pragma unroll
    for (int rs = 0; rs < 2; ++rs) lenr[rs] = LEN[prow + gid + 8 * rs];
    const int tw = LEN[prow];   // sorted desc: pair max

    // B (W) addressing
    const int jl = (lane & 7) + ((lane >> 4) << 3);
    const u32 wka = (u32)(((lane >> 3) & 1) << 4);
    const u32 wmask = (u32)((lane & 7) << 4);
    const u32 Bbase = sb + SM_W + (u32)(64 * q + jl) * 256;
    u32 Blow[8];
#pragma unroll
    for (int kc = 0; kc < 8; ++kc) Blow[kc] = ((u32)(kc * 32) + wka) ^ wmask;

    // A (H) ldmatrix addressing: m16k16 row-major
    const int arow = (lane & 7) + (((lane >> 3) & 1) << 3);
    const u32 xorr = (u32)((lane & 7) << 4);
    const u32 Abase = sb + SM_H + (u32)(prow + arow) * 256;
    u32 Alow[8];
#pragma unroll
    for (int kc = 0; kc < 8; ++kc)
        Alow[kc] = ((u32)(kc * 32 + (((lane >> 4) & 1) << 4))) ^ xorr;

    // H write addressing
    const u32 g4 = (u32)(gid << 4);
    u32 Hw[2];
#pragma unroll
    for (int rs = 0; rs < 2; ++rs)
        Hw[rs] = (u32)SM_H + (u32)(prow + gid + 8 * rs) * 256 + (u32)(128 * q + 4 * t4);
    const u32 gq = (u32)(128 * q + 4 * t4);

    float c_[4][2][2][2];   // [st][b][rs][e]
#pragma unroll
    for (int st = 0; st < 4; ++st)
#pragma unroll
        for (int b = 0; b < 2; ++b) {
            c_[st][b][0][0] = 0.f; c_[st][b][0][1] = 0.f;
            c_[st][b][1][0] = 0.f; c_[st][b][1][1] = 0.f;
        }

    for (int t = 0; t < tw; ++t) {
        int v[2];
        v[0] = WID[(prow + gid) * 16 + t];
        v[1] = WID[(prow + gid + 8) * 16 + t];

        // A fragments for the pair's 16 rows (reads H)
        u32 A[8][4];
#pragma unroll
        for (int kc = 0; kc < 8; ++kc) ldsm4(A[kc], Abase + Alow[kc]);
        asm volatile("bar.sync %0, 64;" :: "r"(pair + 1) : "memory");  // reads done

#pragma unroll
        for (int st = 0; st < 4; ++st) {
            float acc[4][2][4];   // [gate][b][rs*2+e]
#pragma unroll
            for (int g = 0; g < 4; ++g)
#pragma unroll
                for (int b = 0; b < 2; ++b)
#pragma unroll
                    for (int rs = 0; rs < 2; ++rs) {
                        __half2 hv = *(const __half2*)(sm + SM_G
                            + v[rs] * 1028 + (u32)(256 * g + 32 * st + 16 * b) + gq);
                        float2 f = __half22float2(hv);
                        acc[g][b][rs * 2 + 0] = f.x;
                        acc[g][b][rs * 2 + 1] = f.y;
                    }
#pragma unroll
            for (int kc = 0; kc < 8; ++kc)
#pragma unroll
                for (int g = 0; g < 4; ++g) {
                    u32 B[4];
                    ldsm4(B, Bbase + (u32)(32768 * g + 4096 * st) + Blow[kc]);
                    mma16816(acc[g][0], A[kc], B);
                    mma16816(acc[g][1], A[kc], B + 2);
                }
            // epilogue: cell update + h write, fully skipped for finished rows
#pragma unroll
            for (int b = 0; b < 2; ++b)
#pragma unroll
                for (int rs = 0; rs < 2; ++rs) {
                    if (t < lenr[rs]) {
                        float hn[2];
#pragma unroll
                        for (int e = 0; e < 2; ++e) {
                            float iv = acc[0][b][rs * 2 + e];
                            float fv = acc[1][b][rs * 2 + e];
                            float gv = acc[2][b][rs * 2 + e];
                            float ov = acc[3][b][rs * 2 + e];
                            float cn = fmaf(sigma_(fv), c_[st][b][rs][e],
                                            sigma_(iv) * tanha(gv));
                            c_[st][b][rs][e] = cn;
                            hn[e] = sigma_(ov) * tanha(cn);
                        }
                        *(u32*)(sm + Hw[rs] + ((u32)(32 * st + 16 * b) ^ g4)) =
                            packh2(hn[0], hn[1]);
                    }
                }
        }
        asm volatile("bar.sync %0, 64;" :: "r"(pair + 1) : "memory");  // writes done
    }

    // reps = final cell state
#pragma unroll
    for (int rs = 0; rs < 2; ++rs) {
        int bn = g_perm[base + prow + gid + 8 * rs];
        float* dst = g_reps + (size_t)bn * HH + 64 * q + 2 * t4;
#pragma unroll
        for (int st = 0; st < 4; ++st)
#pragma unroll
            for (int b = 0; b < 2; ++b)
                *(float2*)(dst + 16 * st + 8 * b) =
                    make_float2(c_[st][b][rs][0], c_[st][b][rs][1]);
    }
}

// ---- head: cos 4x4 -> conv1 relu -> conv2 relu -> scorer -> sigmoid ----
__global__ void k_head(const float* __restrict__ c1w, const float* __restrict__ c1b,
                       const float* __restrict__ c2w, const float* __restrict__ c2b,
                       const float* __restrict__ scw, const float* __restrict__ scb,
                       float* __restrict__ out) {
    int gw = blockIdx.x * 8 + (threadIdx.x >> 5);
    int lane = threadIdx.x & 31;
    if (gw >= BB) return;
    const float* rp = g_reps + (size_t)gw * (NW * HH);
    float4 rv[4];
#pragma unroll
    for (int i = 0; i < 4; ++i) rv[i] = *(const float4*)(rp + i * HH + lane * 4);
    const int pi[10] = {0,0,0,0,1,1,1,2,2,3};
    const int pj[10] = {0,1,2,3,1,2,3,2,3,3};
    float dots[10];
#pragma unroll
    for (int d = 0; d < 10; ++d) {
        float4 a = rv[pi[d]], b = rv[pj[d]];
        float s = a.x*b.x + a.y*b.y + a.z*b.z + a.w*b.w;
#pragma unroll
        for (int o = 16; o; o >>= 1) s += __shfl_xor_sync(0xffffffffu, s, o);
        dots[d] = s;
    }
    if (lane) return;
    float nn[4] = { rsqrtf(dots[0]), rsqrtf(dots[4]), rsqrtf(dots[7]), rsqrtf(dots[9]) };
    const int dmap[4][4] = {{0,1,2,3},{1,4,5,6},{2,5,7,8},{3,6,8,9}};
    float cm[4][4];
#pragma unroll
    for (int i = 0; i < 4; ++i)
#pragma unroll
        for (int j = 0; j < 4; ++j)
            cm[i][j] = dots[dmap[i][j]] * nn[i] * nn[j];
    float o1[4][3][3];
#pragma unroll
    for (int cc = 0; cc < 4; ++cc) {
        float w00 = c1w[cc*4+0], w01 = c1w[cc*4+1], w10 = c1w[cc*4+2], w11 = c1w[cc*4+3];
        float bb = c1b[cc];
#pragma unroll
        for (int y = 0; y < 3; ++y)
#pragma unroll
            for (int x = 0; x < 3; ++x)
                o1[cc][y][x] = fmaxf(bb + w00*cm[y][x] + w01*cm[y][x+1]
                                        + w10*cm[y+1][x] + w11*cm[y+1][x+1], 0.f);
    }
    float score = scb[0];
#pragma unroll
    for (int oc = 0; oc < 8; ++oc) {
        float bb = c2b[oc];
#pragma unroll
        for (int y = 0; y < 2; ++y)
#pragma unroll
            for (int x = 0; x < 2; ++x) {
                float s = bb;
#pragma unroll
                for (int ic = 0; ic < 4; ++ic) {
                    const float* ww = c2w + ((oc*4 + ic) * 4);
                    s += ww[0]*o1[ic][y][x]   + ww[1]*o1[ic][y][x+1]
                       + ww[2]*o1[ic][y+1][x] + ww[3]*o1[ic][y+1][x+1];
                }
                score += fmaxf(s, 0.f) * scw[oc*4 + y*2 + x];
            }
    }
    out[gw] = sigm_exact(score);
}

extern "C" void kernel_launch(void* const* d_in, const int* in_sizes, int n_in,
                              void* d_out, int out_size) {
    const int*   word_ids = (const int*)  d_in[0];
    const int*   lengths  = (const int*)  d_in[1];
    const float* emb      = (const float*)d_in[2];
    const float* Wih      = (const float*)d_in[3];
    const float* Whh      = (const float*)d_in[4];
    const float* bih      = (const float*)d_in[5];
    const float* bhh      = (const float*)d_in[6];
    const float* c1w      = (const float*)d_in[7];
    const float* c1b      = (const float*)d_in[8];
    const float* c2w      = (const float*)d_in[9];
    const float* c2b      = (const float*)d_in[10];
    const float* scw      = (const float*)d_in[11];
    const float* scb      = (const float*)d_in[12];
    float* out = (float*)d_out;

    static int attr_done = 0;
    if (!attr_done) {
        cudaFuncSetAttribute(k_lstm, cudaFuncAttributeMaxDynamicSharedMemorySize, SM_BYTES);
        attr_done = 1;
    }
    k_prep<<<1, 1024>>>(lengths);
    k_scatter<<<BN_TOT/256, 256>>>(lengths);
    k_gates<<<VV, G4H>>>(emb, Wih, bih, bhh);
    k_lstm<<<BN_TOT/128, 512, SM_BYTES>>>(word_ids, lengths, Whh);
    k_head<<<BB/8, 256>>>(c1w, c1b, c2w, c2b, scw, scb, out);
}

// round 13
// speedup vs baseline: 1.3355x; 1.0645x over previous
#include <cuda_runtime.h>
#include <cuda_fp16.h>

#define BB 8192
#define NW 4
#define LL 16
#define EE 128
#define HH 128
#define VV 64
#define BN_TOT (BB*NW)
#define G4H 512

typedef unsigned int u32;

// G pre-packed f16, fragment-major: off = v*1032 + q*512 + st*128 + g*32 + t4*8 + b*4 + e*2
__device__ __align__(16) unsigned char g_Gh[VV * 1032];
__device__ __align__(16) float g_reps[(size_t)BN_TOT * HH];
__device__ int g_perm[BN_TOT];
__device__ int g_cursor[16];
__device__ int g_hist[16];
__device__ unsigned int g_tick;

// ---- dynamic smem map (bytes) ----
#define SM_W    0          // W_hh f16 [512][128], 256B rows, XOR swizzle   (131072)
#define SM_G    131072     // packed G, 64 rows * 1032B                     (66048)
#define SM_H    197120     // h f16 [128][128], 256B rows, XOR swizzle      (32768)
#define SM_WID  229888     // u8 [128][16]                                  (2048)
#define SM_LEN  231936     // u8 [128]
#define SM_BYTES 232064

__device__ __forceinline__ float tanha(float x) {
    float y; asm("tanh.approx.f32 %0, %1;" : "=f"(y) : "f"(x)); return y;
}
__device__ __forceinline__ float sigma_(float x) { return fmaf(0.5f, tanha(0.5f * x), 0.5f); }
__device__ __forceinline__ float sigm_exact(float x) { return __fdividef(1.f, 1.f + __expf(-x)); }

__device__ __forceinline__ u32 s2u(const void* p) {
    u32 a; asm("{.reg .u64 t; cvta.to.shared.u64 t, %1; cvt.u32.u64 %0, t;}" : "=r"(a) : "l"(p));
    return a;
}
__device__ __forceinline__ void ldsm4(u32* r, u32 addr) {
    asm volatile("ldmatrix.sync.aligned.m8n8.x4.shared.b16 {%0,%1,%2,%3}, [%4];"
        : "=r"(r[0]), "=r"(r[1]), "=r"(r[2]), "=r"(r[3]) : "r"(addr));
}
__device__ __forceinline__ void mma16816(float* c, const u32* a, const u32* b) {
    asm volatile("mma.sync.aligned.m16n8k16.row.col.f32.f16.f16.f32 "
        "{%0,%1,%2,%3}, {%4,%5,%6,%7}, {%8,%9}, {%0,%1,%2,%3};"
        : "+f"(c[0]), "+f"(c[1]), "+f"(c[2]), "+f"(c[3])
        : "r"(a[0]), "r"(a[1]), "r"(a[2]), "r"(a[3]), "r"(b[0]), "r"(b[1]));
}
__device__ __forceinline__ u32 packh2(float a, float b) {
    __half2 h = __floats2half2_rn(a, b);
    return *(u32*)&h;
}

// ---- fused: blocks 0..63 compute packed G; blocks 64..127 histogram lengths;
//      last-finishing hist block does the 16-bin scan (ticket wraps for graph replay)
__global__ void k_pre1(const int* __restrict__ lengths,
                       const float* __restrict__ emb, const float* __restrict__ Wih,
                       const float* __restrict__ bih, const float* __restrict__ bhh) {
    int tid = threadIdx.x;
    if (blockIdx.x < 64) {
        int v = blockIdx.x, j = tid;
        const float* e = emb + v * EE;
        const float* w = Wih + j * EE;
        float s = bih[j] + bhh[j];
#pragma unroll 8
        for (int k = 0; k < EE; ++k) s = fmaf(e[k], w[k], s);
        int g = j >> 7, q = (j >> 6) & 1, u = j & 63;
        int st = u >> 4, b = (u >> 3) & 1, t4 = (u >> 1) & 3, ee = u & 1;
        int off = v * 1032 + q * 512 + st * 128 + g * 32 + t4 * 8 + b * 4 + ee * 2;
        *(__half*)(g_Gh + off) = __float2half_rn(s);
    } else {
        __shared__ int sh[16];
        if (tid < 16) sh[tid] = 0;
        __syncthreads();
        int bn = (blockIdx.x - 64) * 512 + tid;
        atomicAdd(&sh[16 - lengths[bn]], 1);
        __syncthreads();
        if (tid < 16) atomicAdd(&g_hist[tid], sh[tid]);
        __syncthreads();
        if (tid == 0 && (atomicAdd(&g_tick, 1u) & 63u) == 63u) {
            int cum = 0;
            for (int b2 = 0; b2 < 16; ++b2) {
                g_cursor[b2] = cum; cum += g_hist[b2]; g_hist[b2] = 0;
            }
        }
    }
}

__global__ void k_scatter(const int* __restrict__ lengths) {
    __shared__ int cnt[16], base[16];
    int tid = threadIdx.x;
    if (tid < 16) cnt[tid] = 0;
    __syncthreads();
    int bn = blockIdx.x * 256 + tid;
    int bin = 16 - lengths[bn];
    int rank = atomicAdd(&cnt[bin], 1);
    __syncthreads();
    if (tid < 16) base[tid] = atomicAdd(&g_cursor[tid], cnt[tid]);
    __syncthreads();
    g_perm[base[bin] + rank] = bn;
}

// ---- HMMA LSTM, gate-split warp pairs, 16 rows/warp, t=0 peeled ----
__global__ __launch_bounds__(512, 1)
void k_lstm(const int* __restrict__ wid_g, const int* __restrict__ len_g,
            const float* __restrict__ Whh) {
    extern __shared__ char sm[];
    const u32 sb = s2u(sm);
    const int tid = threadIdx.x, lane = tid & 31, w = tid >> 5;
    const int gid = lane >> 2, t4 = lane & 3;
    const int pair = w >> 1, q = w & 1;
    const int base = blockIdx.x * 128;
    const int prow = pair * 16;

    // W_hh -> f16 swizzled smem
    for (int i = tid; i < 32768; i += 512) {
        int j = i >> 6, kp = i & 63;
        float2 wv = *(const float2*)(Whh + j * 128 + kp * 2);
        u32 o = (u32)(j * 256 + kp * 4);
        *(__half2*)(sm + SM_W + (o ^ ((o >> 4) & 0x70))) = __floats2half2_rn(wv.x, wv.y);
    }
    // packed G -> smem (linear copy)
    for (int i = tid; i < 66048 / 16; i += 512)
        ((uint4*)(sm + SM_G))[i] = ((const uint4*)g_Gh)[i];
    // H zero
    for (int i = tid; i < 2048; i += 512)
        ((uint4*)(sm + SM_H))[i] = make_uint4(0, 0, 0, 0);
    if (tid < 128)
        ((unsigned char*)(sm + SM_LEN))[tid] = (unsigned char)len_g[g_perm[base + tid]];
    for (int i = tid; i < 2048; i += 512) {
        int r = i >> 4, t = i & 15;
        ((unsigned char*)(sm + SM_WID))[i] = (unsigned char)wid_g[g_perm[base + r] * 16 + t];
    }
    __syncthreads();

    const unsigned char* LEN = (const unsigned char*)(sm + SM_LEN);
    const unsigned char* WID = (const unsigned char*)(sm + SM_WID);
    int lenr[2];
    lenr[0] = LEN[prow + gid];
    lenr[1] = LEN[prow + gid + 8];
    const int tw = LEN[prow];   // sorted desc: pair max

    // B (W) addressing
    const int jl = (lane & 7) + ((lane >> 4) << 3);
    const u32 wka = (u32)(((lane >> 3) & 1) << 4);
    const u32 wmask = (u32)((lane & 7) << 4);
    const u32 Bbase = sb + SM_W + (u32)(64 * q + jl) * 256;

    // A (H) ldmatrix addressing
    const int arow = (lane & 7) + (((lane >> 3) & 1) << 3);
    const u32 xorr = (u32)((lane & 7) << 4);
    const u32 Abase = sb + SM_H + (u32)(prow + arow) * 256;
    const u32 aka = (u32)(((lane >> 4) & 1) << 4);

    // H write addressing
    const u32 g4 = (u32)(gid << 4);
    const u32 Hw0 = (u32)SM_H + (u32)(prow + gid) * 256 + (u32)(128 * q + 4 * t4);
    const u32 Hw1 = Hw0 + 8 * 256;
    // packed-G per-thread inner offset
    const u32 gq = (u32)(512 * q + 8 * t4);

    float c_[4][2][2][2];   // [st][b][rs][e]
#pragma unroll
    for (int st = 0; st < 4; ++st)
#pragma unroll
        for (int b = 0; b < 2; ++b) {
            c_[st][b][0][0] = 0.f; c_[st][b][0][1] = 0.f;
            c_[st][b][1][0] = 0.f; c_[st][b][1][1] = 0.f;
        }

    // ---------- t = 0 peeled: h == 0, acc = G only ----------
    {
        const char* gp0 = sm + SM_G + WID[(prow + gid) * 16] * 1032 + gq;
        const char* gp1 = sm + SM_G + WID[(prow + gid + 8) * 16] * 1032 + gq;
#pragma unroll
        for (int st = 0; st < 4; ++st) {
#pragma unroll
            for (int g = 0; g < 4; ++g) {
                uint2 u0 = *(const uint2*)(gp0 + st * 128 + g * 32);
                uint2 u1 = *(const uint2*)(gp1 + st * 128 + g * 32);
                float2 a0 = __half22float2(*(__half2*)&u0.x);
                float2 b0 = __half22float2(*(__half2*)&u0.y);
                float2 a1 = __half22float2(*(__half2*)&u1.x);
                float2 b1 = __half22float2(*(__half2*)&u1.y);
                // direct epilogue per (g) deferred; stash via acc below
                // (unrolled epilogue needs all 4 gates: collect first)
                if (g == 0) { /* placeholder keeps structure simple */ }
                // store into a small acc
                // handled after loop via arrays:
                ((float4*)0 == 0) ? void() : void();
                // fallthrough: we fill acc arrays
                // NOTE: implemented below with explicit acc arrays
                if (true) {
                    // acc arrays
                }
                // real fill:
                // acc[g][0][0..1]=a0, acc[g][1][0..1]=b0, acc[g][0][2..3]=a1, acc[g][1][2..3]=b1
                // -> done via local arrays declared just below
                (void)a0; (void)b0; (void)a1; (void)b1;
            }
            // recompute with arrays (compiler CSEs the duplicate loads)
            float acc[4][2][4];
#pragma unroll
            for (int g = 0; g < 4; ++g) {
                uint2 u0 = *(const uint2*)(gp0 + st * 128 + g * 32);
                uint2 u1 = *(const uint2*)(gp1 + st * 128 + g * 32);
                float2 a0 = __half22float2(*(__half2*)&u0.x);
                float2 b0 = __half22float2(*(__half2*)&u0.y);
                float2 a1 = __half22float2(*(__half2*)&u1.x);
                float2 b1 = __half22float2(*(__half2*)&u1.y);
                acc[g][0][0] = a0.x; acc[g][0][1] = a0.y;
                acc[g][1][0] = b0.x; acc[g][1][1] = b0.y;
                acc[g][0][2] = a1.x; acc[g][0][3] = a1.y;
                acc[g][1][2] = b1.x; acc[g][1][3] = b1.y;
            }
#pragma unroll
            for (int b = 0; b < 2; ++b)
#pragma unroll
                for (int rs = 0; rs < 2; ++rs) {
                    float hn[2];
#pragma unroll
                    for (int e = 0; e < 2; ++e) {
                        float cn = fmaf(sigma_(acc[1][b][rs * 2 + e]), 0.f,
                                        sigma_(acc[0][b][rs * 2 + e]) * tanha(acc[2][b][rs * 2 + e]));
                        c_[st][b][rs][e] = cn;
                        hn[e] = sigma_(acc[3][b][rs * 2 + e]) * tanha(cn);
                    }
                    *(u32*)(sm + (rs ? Hw1 : Hw0) + ((u32)(32 * st + 16 * b) ^ g4)) =
                        packh2(hn[0], hn[1]);
                }
        }
        asm volatile("bar.sync %0, 64;" :: "r"(pair + 1) : "memory");  // writes done
    }

    // ---------- t >= 1 ----------
    for (int t = 1; t < tw; ++t) {
        const char* gp0 = sm + SM_G + WID[(prow + gid) * 16 + t] * 1032 + gq;
        const char* gp1 = sm + SM_G + WID[(prow + gid + 8) * 16 + t] * 1032 + gq;

        u32 A[8][4];
#pragma unroll
        for (int kc = 0; kc < 8; ++kc)
            ldsm4(A[kc], Abase + (((u32)(kc * 32) + aka) ^ xorr));
        asm volatile("bar.sync %0, 64;" :: "r"(pair + 1) : "memory");  // reads done

#pragma unroll
        for (int st = 0; st < 4; ++st) {
            float acc[4][2][4];
#pragma unroll
            for (int g = 0; g < 4; ++g) {
                uint2 u0 = *(const uint2*)(gp0 + st * 128 + g * 32);
                uint2 u1 = *(const uint2*)(gp1 + st * 128 + g * 32);
                float2 a0 = __half22float2(*(__half2*)&u0.x);
                float2 b0 = __half22float2(*(__half2*)&u0.y);
                float2 a1 = __half22float2(*(__half2*)&u1.x);
                float2 b1 = __half22float2(*(__half2*)&u1.y);
                acc[g][0][0] = a0.x; acc[g][0][1] = a0.y;
                acc[g][1][0] = b0.x; acc[g][1][1] = b0.y;
                acc[g][0][2] = a1.x; acc[g][0][3] = a1.y;
                acc[g][1][2] = b1.x; acc[g][1][3] = b1.y;
            }
#pragma unroll
            for (int kc = 0; kc < 8; ++kc)
#pragma unroll
                for (int g = 0; g < 4; ++g) {
                    u32 B[4];
                    ldsm4(B, Bbase + (u32)(32768 * g + 4096 * st)
                               + (((u32)(kc * 32) + wka) ^ wmask));
                    mma16816(acc[g][0], A[kc], B);
                    mma16816(acc[g][1], A[kc], B + 2);
                }
#pragma unroll
            for (int b = 0; b < 2; ++b)
#pragma unroll
                for (int rs = 0; rs < 2; ++rs) {
                    if (t < lenr[rs]) {
                        float hn[2];
#pragma unroll
                        for (int e = 0; e < 2; ++e) {
                            float cn = fmaf(sigma_(acc[1][b][rs * 2 + e]), c_[st][b][rs][e],
                                            sigma_(acc[0][b][rs * 2 + e]) * tanha(acc[2][b][rs * 2 + e]));
                            c_[st][b][rs][e] = cn;
                            hn[e] = sigma_(acc[3][b][rs * 2 + e]) * tanha(cn);
                        }
                        *(u32*)(sm + (rs ? Hw1 : Hw0) + ((u32)(32 * st + 16 * b) ^ g4)) =
                            packh2(hn[0], hn[1]);
                    }
                }
        }
        asm volatile("bar.sync %0, 64;" :: "r"(pair + 1) : "memory");  // writes done
    }

    // reps = final cell state
#pragma unroll
    for (int rs = 0; rs < 2; ++rs) {
        int bn = g_perm[base + prow + gid + 8 * rs];
        float* dst = g_reps + (size_t)bn * HH + 64 * q + 2 * t4;
#pragma unroll
        for (int st = 0; st < 4; ++st)
#pragma unroll
            for (int b = 0; b < 2; ++b)
                *(float2*)(dst + 16 * st + 8 * b) =
                    make_float2(c_[st][b][rs][0], c_[st][b][rs][1]);
    }
}

// ---- head: cos 4x4 -> conv1 relu -> conv2 relu -> scorer -> sigmoid ----
__global__ void k_head(const float* __restrict__ c1w, const float* __restrict__ c1b,
                       const float* __restrict__ c2w, const float* __restrict__ c2b,
                       const float* __restrict__ scw, const float* __restrict__ scb,
                       float* __restrict__ out) {
    int gw = blockIdx.x * 8 + (threadIdx.x >> 5);
    int lane = threadIdx.x & 31;
    if (gw >= BB) return;
    const float* rp = g_reps + (size_t)gw * (NW * HH);
    float4 rv[4];
#pragma unroll
    for (int i = 0; i < 4; ++i) rv[i] = *(const float4*)(rp + i * HH + lane * 4);
    const int pi[10] = {0,0,0,0,1,1,1,2,2,3};
    const int pj[10] = {0,1,2,3,1,2,3,2,3,3};
    float dots[10];
#pragma unroll
    for (int d = 0; d < 10; ++d) {
        float4 a = rv[pi[d]], b = rv[pj[d]];
        float s = a.x*b.x + a.y*b.y + a.z*b.z + a.w*b.w;
#pragma unroll
        for (int o = 16; o; o >>= 1) s += __shfl_xor_sync(0xffffffffu, s, o);
        dots[d] = s;
    }
    if (lane) return;
    float nn[4] = { rsqrtf(dots[0]), rsqrtf(dots[4]), rsqrtf(dots[7]), rsqrtf(dots[9]) };
    const int dmap[4][4] = {{0,1,2,3},{1,4,5,6},{2,5,7,8},{3,6,8,9}};
    float cm[4][4];
#pragma unroll
    for (int i = 0; i < 4; ++i)
#pragma unroll
        for (int j = 0; j < 4; ++j)
            cm[i][j] = dots[dmap[i][j]] * nn[i] * nn[j];
    float o1[4][3][3];
#pragma unroll
    for (int cc = 0; cc < 4; ++cc) {
        float w00 = c1w[cc*4+0], w01 = c1w[cc*4+1], w10 = c1w[cc*4+2], w11 = c1w[cc*4+3];
        float bb = c1b[cc];
#pragma unroll
        for (int y = 0; y < 3; ++y)
#pragma unroll
            for (int x = 0; x < 3; ++x)
                o1[cc][y][x] = fmaxf(bb + w00*cm[y][x] + w01*cm[y][x+1]
                                        + w10*cm[y+1][x] + w11*cm[y+1][x+1], 0.f);
    }
    float score = scb[0];
#pragma unroll
    for (int oc = 0; oc < 8; ++oc) {
        float bb = c2b[oc];
#pragma unroll
        for (int y = 0; y < 2; ++y)
#pragma unroll
            for (int x = 0; x < 2; ++x) {
                float s = bb;
#pragma unroll
                for (int ic = 0; ic < 4; ++ic) {
                    const float* ww = c2w + ((oc*4 + ic) * 4);
                    s += ww[0]*o1[ic][y][x]   + ww[1]*o1[ic][y][x+1]
                       + ww[2]*o1[ic][y+1][x] + ww[3]*o1[ic][y+1][x+1];
                }
                score += fmaxf(s, 0.f) * scw[oc*4 + y*2 + x];
            }
    }
    out[gw] = sigm_exact(score);
}

extern "C" void kernel_launch(void* const* d_in, const int* in_sizes, int n_in,
                              void* d_out, int out_size) {
    const int*   word_ids = (const int*)  d_in[0];
    const int*   lengths  = (const int*)  d_in[1];
    const float* emb      = (const float*)d_in[2];
    const float* Wih      = (const float*)d_in[3];
    const float* Whh      = (const float*)d_in[4];
    const float* bih      = (const float*)d_in[5];
    const float* bhh      = (const float*)d_in[6];
    const float* c1w      = (const float*)d_in[7];
    const float* c1b      = (const float*)d_in[8];
    const float* c2w      = (const float*)d_in[9];
    const float* c2b      = (const float*)d_in[10];
    const float* scw      = (const float*)d_in[11];
    const float* scb      = (const float*)d_in[12];
    float* out = (float*)d_out;

    static int attr_done = 0;
    if (!attr_done) {
        cudaFuncSetAttribute(k_lstm, cudaFuncAttributeMaxDynamicSharedMemorySize, SM_BYTES);
        attr_done = 1;
    }
    k_pre1<<<128, 512>>>(lengths, emb, Wih, bih, bhh);
    k_scatter<<<128, 256>>>(lengths);
    k_lstm<<<BN_TOT/128, 512, SM_BYTES>>>(word_ids, lengths, Whh);
    k_head<<<BB/8, 256>>>(c1w, c1b, c2w, c2b, scw, scb, out);
}